// round 12
// baseline (speedup 1.0000x reference)
#include <cuda_runtime.h>
#include <math_constants.h>

// Problem constants
#define BB 2
#define CIN 3
#define HH 32
#define WW 32
#define CM 32      // mid channels
#define HQ 16      // mid spatial
#define CO 64      // out channels
#define HP 8       // out spatial
#define NP 64      // HP*HP
#define NI 1024    // HH*WW
#define NE 512     // num embeddings

// Scratch in device globals (no allocations allowed)
__device__ float g_xw1[BB][HQ][HQ][16][CM];  // per-tap conv1 partials, [k1][m]
__device__ float g_y1[BB][HQ][HQ][CM];       // relu(conv1)
__device__ float g_y[BB][NP][CO];            // relu(conv2)
__device__ float g_v[BB][NP][16][16];        // [k2][k1]
__device__ float g_ymask[BB][NP][CO];
__device__ float g_w2t[16][CM][CO];          // w2 transposed: [k2][m][o]

// ---------------------------------------------------------------------------
// Shuffle-based block reductions over 512 threads
__device__ __forceinline__ float blockMax512(float v, float* red16, int t) {
#pragma unroll
    for (int off = 16; off > 0; off >>= 1)
        v = fmaxf(v, __shfl_xor_sync(0xffffffffu, v, off));
    if ((t & 31) == 0) red16[t >> 5] = v;
    __syncthreads();
    if (t < 32) {
        float w = (t < 16) ? red16[t] : -CUDART_INF_F;
#pragma unroll
        for (int off = 8; off > 0; off >>= 1)
            w = fmaxf(w, __shfl_xor_sync(0xffffffffu, w, off));
        if (t == 0) red16[0] = w;
    }
    __syncthreads();
    return red16[0];
}
__device__ __forceinline__ float blockSum512(float v, float* red16, int t) {
#pragma unroll
    for (int off = 16; off > 0; off >>= 1)
        v += __shfl_xor_sync(0xffffffffu, v, off);
    if ((t & 31) == 0) red16[t >> 5] = v;
    __syncthreads();
    if (t < 32) {
        float w = (t < 16) ? red16[t] : 0.f;
#pragma unroll
        for (int off = 8; off > 0; off >>= 1)
            w += __shfl_xor_sync(0xffffffffu, w, off);
        if (t == 0) red16[0] = w;
    }
    __syncthreads();
    return red16[0];
}

// ---------------------------------------------------------------------------
// Kernel A: conv1 per-tap partials + relu(conv1); w2t transpose; zero ymask
// grid = 128 blocks, 256 threads
__global__ void __launch_bounds__(256, 1)
kA(const float* __restrict__ x, const float* __restrict__ w1,
   const float* __restrict__ b1, const float* __restrict__ w2) {
    int gid = blockIdx.x * 256 + threadIdx.x;  // 0..32767
    {
        int k2 = gid >> 11, m = (gid >> 6) & 31, o = gid & 63;
        g_w2t[k2][m][o] = w2[(o * CM + m) * 16 + k2];
    }
    if (gid < BB * NP * CO) (&g_ymask[0][0][0])[gid] = 0.f;
    if (gid < BB * HQ * HQ * CM) {
        int m = gid & 31;
        int site = gid >> 5;
        int b = site >> 8;
        int q = site & 255;
        int qh = q >> 4, qw = q & 15;
        float acc = b1[m];
#pragma unroll
        for (int k = 0; k < 16; k++) {
            int kh = k >> 2, kw = k & 3;
            int xh = 2 * qh - 1 + kh, xw = 2 * qw - 1 + kw;
            float vv = 0.f;
            if (xh >= 0 && xh < HH && xw >= 0 && xw < WW) {
#pragma unroll
                for (int c = 0; c < CIN; c++)
                    vv += w1[(m * CIN + c) * 16 + k] *
                          x[((b * CIN + c) * HH + xh) * WW + xw];
            }
            g_xw1[b][qh][qw][k][m] = vv;
            acc += vv;
        }
        g_y1[b][qh][qw][m] = fmaxf(acc, 0.f);
    }
}

// ---------------------------------------------------------------------------
// Kernel BCDE: conv2 + relu + hopfield -> rm (smem), then s -> v, per (b,p)
// grid = BB*NP = 128 blocks, 512 threads
// DE's s now reads g_w2t rows (contiguous per-thread) -> no tile loop, no
// extra barriers, smem down to ~11KB.
__global__ void __launch_bounds__(512, 1)
kBCDE(const float* __restrict__ w1, const float* __restrict__ w2,
      const float* __restrict__ b2, const float* __restrict__ Km,
      const float* __restrict__ Vm) {
    __shared__ float yv[CO];
    __shared__ float wexp[NE];
    __shared__ float red2[8][CO];
    __shared__ float red16[16];
    __shared__ float y1ps[16][CM];   // [site][m], OOB sites zeroed
    __shared__ float rm_s[CO];
    __shared__ float w1st[16][33];   // [k1][m], padded
    __shared__ float smT[16][33];    // [k2][m], padded
    int t = threadIdx.x;
    int blk = blockIdx.x;
    int b = blk / NP, p = blk % NP;
    int ph = p / HP, pw = p % HP;

    // ---- prologue: w1st (independent of kA) ----
    {
        int m = t >> 4, k = t & 15;
        if (m < CM) {
            float acc = 0.f;
#pragma unroll
            for (int c = 0; c < CIN; c++) acc += w1[(m * CIN + c) * 16 + k];
            w1st[k][m] = acc;
        }
    }

    // ---- load y1 patch: one thread per (site, m); coalesced over m ----
    {
        int sk = t >> 5, m = t & 31;
        int qh = 2 * ph - 1 + (sk >> 2);
        int qw = 2 * pw - 1 + (sk & 3);
        float vv = 0.f;
        if (qh >= 0 && qh < HQ && qw >= 0 && qw < HQ) vv = g_y1[b][qh][qw][m];
        y1ps[sk][m] = vv;
    }
    __syncthreads();

    // ---- conv2: o = t&63, g8 = t>>6 handles elements g8*64..+63 of w2 row ----
    {
        int o = t & 63, g8 = t >> 6;
        const float4* w2v = reinterpret_cast<const float4*>(w2 + o * 512 + g8 * 64);
        float acc = 0.f;
#pragma unroll
        for (int j4 = 0; j4 < 16; j4++) {
            float4 wv = w2v[j4];
            int e = g8 * 64 + j4 * 4;
            acc += wv.x * y1ps[(e + 0) & 15][(e + 0) >> 4];
            acc += wv.y * y1ps[(e + 1) & 15][(e + 1) >> 4];
            acc += wv.z * y1ps[(e + 2) & 15][(e + 2) >> 4];
            acc += wv.w * y1ps[(e + 3) & 15][(e + 3) >> 4];
        }
        red2[g8][o] = acc;
    }
    __syncthreads();
    if (t < CO) {
        float acc = b2[t];
#pragma unroll
        for (int g = 0; g < 8; g++) acc += red2[g][t];
        float yy = fmaxf(acc, 0.f);
        yv[t] = yy;
        g_y[b][p][t] = yy;
    }
    __syncthreads();

    // ---- hopfield softmax: 1 key per thread, raw Km row via float4 ----
    float l0;
    {
        const float4* kv = reinterpret_cast<const float4*>(Km + t * CO);
        float acc = 0.f;
#pragma unroll
        for (int j = 0; j < 16; j++) {
            float4 w4 = kv[j];
            acc += w4.x * yv[4 * j] + w4.y * yv[4 * j + 1] +
                   w4.z * yv[4 * j + 2] + w4.w * yv[4 * j + 3];
        }
        l0 = 0.125f * acc;
    }
    float lmax = blockMax512(l0, red16, t);
    float e0 = expf(l0 - lmax);
    wexp[t] = e0;
    float tot = blockSum512(e0, red16, t);
    float inv = 1.f / tot;
    __syncthreads();
    {
        int o = t & 63, g8 = t >> 6;
        float acc = 0.f;
        int k0 = g8 * 64;
#pragma unroll 8
        for (int kk = 0; kk < 64; kk++)
            acc += wexp[k0 + kk] * Vm[(k0 + kk) * CO + o];
        red2[g8][o] = acc;
    }
    __syncthreads();
    if (t < CO) {
        float e = 0.f;
#pragma unroll
        for (int g = 0; g < 8; g++) e += red2[g][t];
        e *= inv;
        float yy = yv[t];
        rm_s[t] = (yy > 0.f) ? 2.f * (yy - e) : 0.f;
    }
    __syncthreads();

    // ---- DE: s[m][k2] = sum_o rm[o]*w2t[k2][m][o]; contiguous per-thread ----
    {
        int m = t >> 4, k2 = t & 15;
        const float4* wv = reinterpret_cast<const float4*>(&g_w2t[k2][m][0]);
        float sacc = 0.f;
#pragma unroll
        for (int j = 0; j < 16; j++) {
            float4 w4 = wv[j];
            sacc += w4.x * rm_s[4 * j] + w4.y * rm_s[4 * j + 1] +
                    w4.z * rm_s[4 * j + 2] + w4.w * rm_s[4 * j + 3];
        }
        smT[k2][m] = (y1ps[k2][m] > 0.f) ? sacc : 0.f;
    }
    __syncthreads();
    if (t < 256) {
        int k2 = t >> 4, k1 = t & 15;
        float a2 = 0.f;
#pragma unroll 8
        for (int m = 0; m < CM; m++)
            a2 += smT[k2][m] * w1st[k1][m];
        g_v[b][p][k2][k1] = a2;
    }
}

// ---------------------------------------------------------------------------
// Kernel FG: argmin + scatter, 4 pixels per block (all same row ih)
// grid = BB*NI/4 = 512 blocks, 256 threads
__global__ void __launch_bounds__(256, 1)
kFG() {
    __shared__ float am_s[4][4][32];
    __shared__ int selp[4];
    __shared__ float we_s[8];
    __shared__ int wp_s[8];
    int t = threadIdx.x;
    int g4 = t >> 6;
    int pix0 = blockIdx.x * 4;
    int i0 = pix0 & 1023;
    int ih = i0 >> 5;
    int qh0 = (ih + 1) >> 1;

    // ---- argmin: thread t = g4*64 + p ----
    {
        int p = t & 63;
        int pixa = pix0 + g4;
        int ba = pixa >> 10;
        int ia = pixa & 1023;
        int iwa = ia & 31;
        int qw0a = (iwa + 1) >> 1;
        int pha = p >> 3, pwa = p & 7;
        float e = 0.f;
#pragma unroll
        for (int qc = 0; qc < 2; qc++) {
            int qh = qh0 - qc;
            int k2h = qh - 2 * pha + 1;
            if (qh < 0 || qh >= HQ || k2h < 0 || k2h > 3) continue;
            int k1h = ih + 1 - 2 * qh;
#pragma unroll
            for (int dqw = 0; dqw < 2; dqw++) {
                int qw = qw0a - dqw;
                int k2w = qw - 2 * pwa + 1;
                if (qw < 0 || qw >= HQ || k2w < 0 || k2w > 3) continue;
                e += g_v[ba][p][k2h * 4 + k2w][k1h * 4 + (iwa + 1 - 2 * qw)];
            }
        }
        float be = e;
        int bp = p;
#pragma unroll
        for (int off = 16; off > 0; off >>= 1) {
            float eo = __shfl_xor_sync(0xffffffffu, be, off);
            int po = __shfl_xor_sync(0xffffffffu, bp, off);
            if (eo < be || (eo == be && po < bp)) { be = eo; bp = po; }
        }
        if ((t & 31) == 0) { we_s[t >> 5] = be; wp_s[t >> 5] = bp; }
    }
    __syncthreads();
    if (t < 4) {
        float e0 = we_s[t * 2], e1 = we_s[t * 2 + 1];
        int p0 = wp_s[t * 2], p1 = wp_s[t * 2 + 1];
        selp[t] = (e1 < e0 || (e1 == e0 && p1 < p0)) ? p1 : p0;
    }
    __syncthreads();

    // ---- scatter contrib into ymask ----
    int o = t & 63;
    int pix = pix0 + g4;
    int b = pix >> 10;
    int i = pix & 1023;
    int iw = i & 31;
    int qw0 = (iw + 1) >> 1;
    int p = selp[g4];
    int ph = p >> 3, pw = p & 7;
#pragma unroll
    for (int rep = 0; rep < 2; rep++) {
        int e2 = rep * 64 + o;
        int qc = e2 >> 5, m = e2 & 31;
        int qh = qh0 - (qc >> 1), qw = qw0 - (qc & 1);
        float vv = 0.f;
        if (qh >= 0 && qh < HQ && qw >= 0 && qw < HQ) {
            int k2h = qh - 2 * ph + 1, k2w = qw - 2 * pw + 1;
            if (k2h >= 0 && k2h <= 3 && k2w >= 0 && k2w <= 3) {
                if (g_y1[b][qh][qw][m] > 0.f) {
                    int k1 = (ih + 1 - 2 * qh) * 4 + (iw + 1 - 2 * qw);
                    vv = g_xw1[b][qh][qw][k1][m];
                }
            }
        }
        am_s[g4][qc][m] = vv;
    }
    __syncthreads();
    float yy = g_y[b][p][o];
    if (yy > 0.f) {
        float acc = 0.f;
#pragma unroll
        for (int qc = 0; qc < 4; qc++) {
            int qh = qh0 - (qc >> 1), qw = qw0 - (qc & 1);
            if (qh < 0 || qh >= HQ || qw < 0 || qw >= HQ) continue;
            int k2h = qh - 2 * ph + 1, k2w = qw - 2 * pw + 1;
            if (k2h < 0 || k2h > 3 || k2w < 0 || k2w > 3) continue;
            int k2 = k2h * 4 + k2w;
#pragma unroll 8
            for (int m = 0; m < CM; m++)
                acc += g_w2t[k2][m][o] * am_s[g4][qc][m];
        }
        if (acc != 0.f) atomicAdd(&g_ymask[b][p][o], acc);
    }
}

// ---------------------------------------------------------------------------
// Kernel H: final hopfield on y_masked -> output (B, CO, HP, HP)
// grid = BB*NP = 128 blocks, 512 threads; raw Km float4 rows
__global__ void __launch_bounds__(512, 1)
kH(const float* __restrict__ Km, const float* __restrict__ Vm,
   float* __restrict__ out) {
    int blk = blockIdx.x;
    int b = blk / NP, p = blk % NP;
    __shared__ float yv[CO];
    __shared__ float wexp[NE];
    __shared__ float red16[16];
    __shared__ float red2[8][CO];
    int t = threadIdx.x;
    if (t < CO) yv[t] = g_ymask[b][p][t];
    __syncthreads();
    float l0;
    {
        const float4* kv = reinterpret_cast<const float4*>(Km + t * CO);
        float acc = 0.f;
#pragma unroll
        for (int j = 0; j < 16; j++) {
            float4 w4 = kv[j];
            acc += w4.x * yv[4 * j] + w4.y * yv[4 * j + 1] +
                   w4.z * yv[4 * j + 2] + w4.w * yv[4 * j + 3];
        }
        l0 = 0.125f * acc;
    }
    float lmax = blockMax512(l0, red16, t);
    float e0 = expf(l0 - lmax);
    wexp[t] = e0;
    float tot = blockSum512(e0, red16, t);
    float inv = 1.f / tot;
    __syncthreads();
    {
        int o = t & 63, g8 = t >> 6;
        float acc = 0.f;
        int k0 = g8 * 64;
#pragma unroll 8
        for (int kk = 0; kk < 64; kk++)
            acc += wexp[k0 + kk] * Vm[(k0 + kk) * CO + o];
        red2[g8][o] = acc;
    }
    __syncthreads();
    if (t < CO) {
        float acc = 0.f;
#pragma unroll
        for (int g = 0; g < 8; g++) acc += red2[g][t];
        out[(b * CO + t) * NP + p] = acc * inv;
    }
}

// ---------------------------------------------------------------------------
extern "C" void kernel_launch(void* const* d_in, const int* in_sizes, int n_in,
                              void* d_out, int out_size) {
    const float* x  = (const float*)d_in[0];  // (2,3,32,32)
    const float* w1 = (const float*)d_in[1];  // (32,3,4,4)
    const float* b1 = (const float*)d_in[2];  // (32,)
    const float* w2 = (const float*)d_in[3];  // (64,32,4,4)
    const float* b2 = (const float*)d_in[4];  // (64,)
    const float* Km = (const float*)d_in[5];  // (512,64)
    const float* Vm = (const float*)d_in[6];  // (512,64)
    float* out = (float*)d_out;               // (2,64,8,8)

    kA<<<128, 256>>>(x, w1, b1, w2);
    kBCDE<<<BB * NP, 512>>>(w1, w2, b2, Km, Vm);
    kFG<<<BB * NI / 4, 256>>>();
    kH<<<BB * NP, 512>>>(Km, Vm, out);
}

// round 14
// speedup vs baseline: 1.0500x; 1.0500x over previous
#include <cuda_runtime.h>
#include <math_constants.h>

// Problem constants
#define BB 2
#define CIN 3
#define HH 32
#define WW 32
#define CM 32      // mid channels
#define HQ 16      // mid spatial
#define CO 64      // out channels
#define HP 8       // out spatial
#define NP 64      // HP*HP
#define NI 1024    // HH*WW
#define NE 512     // num embeddings

// Scratch in device globals (no allocations allowed)
__device__ float g_xw1[BB][HQ][HQ][16][CM];  // per-tap conv1 partials, [k1][m]
__device__ float g_y1[BB][HQ][HQ][CM];       // relu(conv1)
__device__ float g_y[BB][NP][CO];            // relu(conv2)
__device__ float g_v[BB][NP][16][16];        // [k2][k1]
__device__ float g_ymask[BB][NP][CO];
__device__ float g_w2t[16][CM][CO];          // w2 transposed: [k2][m][o]
__device__ float g_KmT[CO][NE];              // K transposed: [o][k] (for kH)

// ---------------------------------------------------------------------------
// Shuffle-based block reductions over 512 threads
__device__ __forceinline__ float blockMax512(float v, float* red16, int t) {
#pragma unroll
    for (int off = 16; off > 0; off >>= 1)
        v = fmaxf(v, __shfl_xor_sync(0xffffffffu, v, off));
    if ((t & 31) == 0) red16[t >> 5] = v;
    __syncthreads();
    if (t < 32) {
        float w = (t < 16) ? red16[t] : -CUDART_INF_F;
#pragma unroll
        for (int off = 8; off > 0; off >>= 1)
            w = fmaxf(w, __shfl_xor_sync(0xffffffffu, w, off));
        if (t == 0) red16[0] = w;
    }
    __syncthreads();
    return red16[0];
}
__device__ __forceinline__ float blockSum512(float v, float* red16, int t) {
#pragma unroll
    for (int off = 16; off > 0; off >>= 1)
        v += __shfl_xor_sync(0xffffffffu, v, off);
    if ((t & 31) == 0) red16[t >> 5] = v;
    __syncthreads();
    if (t < 32) {
        float w = (t < 16) ? red16[t] : 0.f;
#pragma unroll
        for (int off = 8; off > 0; off >>= 1)
            w += __shfl_xor_sync(0xffffffffu, w, off);
        if (t == 0) red16[0] = w;
    }
    __syncthreads();
    return red16[0];
}

// ---------------------------------------------------------------------------
// Kernel A: conv1 per-tap partials + relu(conv1); transposes; zero ymask
// grid = 128 blocks, 256 threads (identical to round-8 champion)
__global__ void __launch_bounds__(256, 1)
kA(const float* __restrict__ x, const float* __restrict__ w1,
   const float* __restrict__ b1, const float* __restrict__ w2,
   const float* __restrict__ Km) {
    int gid = blockIdx.x * 256 + threadIdx.x;  // 0..32767
    {
        int k2 = gid >> 11, m = (gid >> 6) & 31, o = gid & 63;
        g_w2t[k2][m][o] = w2[(o * CM + m) * 16 + k2];
        int o2 = gid >> 9, kk = gid & 511;
        g_KmT[o2][kk] = Km[kk * CO + o2];
    }
    if (gid < BB * NP * CO) (&g_ymask[0][0][0])[gid] = 0.f;
    if (gid < BB * HQ * HQ * CM) {
        int m = gid & 31;
        int site = gid >> 5;
        int b = site >> 8;
        int q = site & 255;
        int qh = q >> 4, qw = q & 15;
        float acc = b1[m];
#pragma unroll
        for (int k = 0; k < 16; k++) {
            int kh = k >> 2, kw = k & 3;
            int xh = 2 * qh - 1 + kh, xw = 2 * qw - 1 + kw;
            float vv = 0.f;
            if (xh >= 0 && xh < HH && xw >= 0 && xw < WW) {
#pragma unroll
                for (int c = 0; c < CIN; c++)
                    vv += w1[(m * CIN + c) * 16 + k] *
                          x[((b * CIN + c) * HH + xh) * WW + xw];
            }
            g_xw1[b][qh][qw][k][m] = vv;
            acc += vv;
        }
        g_y1[b][qh][qw][m] = fmaxf(acc, 0.f);
    }
}

// ---------------------------------------------------------------------------
// Kernel BCDE: conv2 + relu + hopfield -> rm (smem), then s -> v, per (b,p)
// grid = BB*NP = 128 blocks, 512 threads
// ONLY change vs round-8: DE's s reads g_w2t rows (contiguous per-thread)
// instead of the 4-iteration smem tile loop. smem 39KB -> ~11KB, -8 barriers.
__global__ void __launch_bounds__(512, 1)
kBCDE(const float* __restrict__ w1, const float* __restrict__ w2,
      const float* __restrict__ b2, const float* __restrict__ Km,
      const float* __restrict__ Vm) {
    __shared__ float yv[CO];
    __shared__ float wexp[NE];
    __shared__ float red2[8][CO];
    __shared__ float red16[16];
    __shared__ float y1ps[16][CM];   // [site][m], OOB sites zeroed
    __shared__ float rm_s[CO];
    __shared__ float w1st[16][33];   // [k1][m], padded
    __shared__ float smT[16][33];    // [k2][m], padded
    int t = threadIdx.x;
    int blk = blockIdx.x;
    int b = blk / NP, p = blk % NP;
    int ph = p / HP, pw = p % HP;

    // ---- prologue: w1st (independent of kA) ----
    {
        int m = t >> 4, k = t & 15;
        if (m < CM) {
            float acc = 0.f;
#pragma unroll
            for (int c = 0; c < CIN; c++) acc += w1[(m * CIN + c) * 16 + k];
            w1st[k][m] = acc;
        }
    }

    // ---- load y1 patch: one thread per (site, m); coalesced over m ----
    {
        int sk = t >> 5, m = t & 31;
        int qh = 2 * ph - 1 + (sk >> 2);
        int qw = 2 * pw - 1 + (sk & 3);
        float vv = 0.f;
        if (qh >= 0 && qh < HQ && qw >= 0 && qw < HQ) vv = g_y1[b][qh][qw][m];
        y1ps[sk][m] = vv;
    }
    __syncthreads();

    // ---- conv2: o = t&63, g8 = t>>6 handles elements g8*64..+63 of w2 row ----
    {
        int o = t & 63, g8 = t >> 6;
        const float4* w2v = reinterpret_cast<const float4*>(w2 + o * 512 + g8 * 64);
        float acc = 0.f;
#pragma unroll
        for (int j4 = 0; j4 < 16; j4++) {
            float4 wv = w2v[j4];
            int e = g8 * 64 + j4 * 4;
            acc += wv.x * y1ps[(e + 0) & 15][(e + 0) >> 4];
            acc += wv.y * y1ps[(e + 1) & 15][(e + 1) >> 4];
            acc += wv.z * y1ps[(e + 2) & 15][(e + 2) >> 4];
            acc += wv.w * y1ps[(e + 3) & 15][(e + 3) >> 4];
        }
        red2[g8][o] = acc;
    }
    __syncthreads();
    if (t < CO) {
        float acc = b2[t];
#pragma unroll
        for (int g = 0; g < 8; g++) acc += red2[g][t];
        float yy = fmaxf(acc, 0.f);
        yv[t] = yy;
        g_y[b][p][t] = yy;
    }
    __syncthreads();

    // ---- hopfield softmax: 1 key per thread, raw Km row via float4 ----
    float l0;
    {
        const float4* kv = reinterpret_cast<const float4*>(Km + t * CO);
        float acc = 0.f;
#pragma unroll
        for (int j = 0; j < 16; j++) {
            float4 w4 = kv[j];
            acc += w4.x * yv[4 * j] + w4.y * yv[4 * j + 1] +
                   w4.z * yv[4 * j + 2] + w4.w * yv[4 * j + 3];
        }
        l0 = 0.125f * acc;
    }
    float lmax = blockMax512(l0, red16, t);
    float e0 = expf(l0 - lmax);
    wexp[t] = e0;
    float tot = blockSum512(e0, red16, t);
    float inv = 1.f / tot;
    __syncthreads();
    {
        int o = t & 63, g8 = t >> 6;
        float acc = 0.f;
        int k0 = g8 * 64;
#pragma unroll 8
        for (int kk = 0; kk < 64; kk++)
            acc += wexp[k0 + kk] * Vm[(k0 + kk) * CO + o];
        red2[g8][o] = acc;
    }
    __syncthreads();
    if (t < CO) {
        float e = 0.f;
#pragma unroll
        for (int g = 0; g < 8; g++) e += red2[g][t];
        e *= inv;
        float yy = yv[t];
        rm_s[t] = (yy > 0.f) ? 2.f * (yy - e) : 0.f;
    }
    __syncthreads();

    // ---- DE: s[m][k2] = sum_o rm[o]*w2t[k2][m][o]; contiguous per-thread ----
    {
        int m = t >> 4, k2 = t & 15;
        const float4* wv = reinterpret_cast<const float4*>(&g_w2t[k2][m][0]);
        float sacc = 0.f;
#pragma unroll
        for (int j = 0; j < 16; j++) {
            float4 w4 = wv[j];
            sacc += w4.x * rm_s[4 * j] + w4.y * rm_s[4 * j + 1] +
                    w4.z * rm_s[4 * j + 2] + w4.w * rm_s[4 * j + 3];
        }
        smT[k2][m] = (y1ps[k2][m] > 0.f) ? sacc : 0.f;
    }
    __syncthreads();
    if (t < 256) {
        int k2 = t >> 4, k1 = t & 15;
        float a2 = 0.f;
#pragma unroll 8
        for (int m = 0; m < CM; m++)
            a2 += smT[k2][m] * w1st[k1][m];
        g_v[b][p][k2][k1] = a2;
    }
}

// ---------------------------------------------------------------------------
// Kernel FG: argmin + scatter, 4 pixels per block (all same row ih)
// grid = BB*NI/4 = 512 blocks, 256 threads (identical to round-8 champion)
__global__ void __launch_bounds__(256, 1)
kFG() {
    __shared__ float am_s[4][4][32];
    __shared__ int selp[4];
    __shared__ float we_s[8];
    __shared__ int wp_s[8];
    int t = threadIdx.x;
    int g4 = t >> 6;
    int pix0 = blockIdx.x * 4;
    int i0 = pix0 & 1023;
    int ih = i0 >> 5;
    int qh0 = (ih + 1) >> 1;

    // ---- argmin: thread t = g4*64 + p ----
    {
        int p = t & 63;
        int pixa = pix0 + g4;
        int ba = pixa >> 10;
        int ia = pixa & 1023;
        int iwa = ia & 31;
        int qw0a = (iwa + 1) >> 1;
        int pha = p >> 3, pwa = p & 7;
        float e = 0.f;
#pragma unroll
        for (int qc = 0; qc < 2; qc++) {
            int qh = qh0 - qc;
            int k2h = qh - 2 * pha + 1;
            if (qh < 0 || qh >= HQ || k2h < 0 || k2h > 3) continue;
            int k1h = ih + 1 - 2 * qh;
#pragma unroll
            for (int dqw = 0; dqw < 2; dqw++) {
                int qw = qw0a - dqw;
                int k2w = qw - 2 * pwa + 1;
                if (qw < 0 || qw >= HQ || k2w < 0 || k2w > 3) continue;
                e += g_v[ba][p][k2h * 4 + k2w][k1h * 4 + (iwa + 1 - 2 * qw)];
            }
        }
        float be = e;
        int bp = p;
#pragma unroll
        for (int off = 16; off > 0; off >>= 1) {
            float eo = __shfl_xor_sync(0xffffffffu, be, off);
            int po = __shfl_xor_sync(0xffffffffu, bp, off);
            if (eo < be || (eo == be && po < bp)) { be = eo; bp = po; }
        }
        if ((t & 31) == 0) { we_s[t >> 5] = be; wp_s[t >> 5] = bp; }
    }
    __syncthreads();
    if (t < 4) {
        float e0 = we_s[t * 2], e1 = we_s[t * 2 + 1];
        int p0 = wp_s[t * 2], p1 = wp_s[t * 2 + 1];
        selp[t] = (e1 < e0 || (e1 == e0 && p1 < p0)) ? p1 : p0;
    }
    __syncthreads();

    // ---- scatter contrib into ymask ----
    int o = t & 63;
    int pix = pix0 + g4;
    int b = pix >> 10;
    int i = pix & 1023;
    int iw = i & 31;
    int qw0 = (iw + 1) >> 1;
    int p = selp[g4];
    int ph = p >> 3, pw = p & 7;
#pragma unroll
    for (int rep = 0; rep < 2; rep++) {
        int e2 = rep * 64 + o;
        int qc = e2 >> 5, m = e2 & 31;
        int qh = qh0 - (qc >> 1), qw = qw0 - (qc & 1);
        float vv = 0.f;
        if (qh >= 0 && qh < HQ && qw >= 0 && qw < HQ) {
            int k2h = qh - 2 * ph + 1, k2w = qw - 2 * pw + 1;
            if (k2h >= 0 && k2h <= 3 && k2w >= 0 && k2w <= 3) {
                if (g_y1[b][qh][qw][m] > 0.f) {
                    int k1 = (ih + 1 - 2 * qh) * 4 + (iw + 1 - 2 * qw);
                    vv = g_xw1[b][qh][qw][k1][m];
                }
            }
        }
        am_s[g4][qc][m] = vv;
    }
    __syncthreads();
    float yy = g_y[b][p][o];
    if (yy > 0.f) {
        float acc = 0.f;
#pragma unroll
        for (int qc = 0; qc < 4; qc++) {
            int qh = qh0 - (qc >> 1), qw = qw0 - (qc & 1);
            if (qh < 0 || qh >= HQ || qw < 0 || qw >= HQ) continue;
            int k2h = qh - 2 * ph + 1, k2w = qw - 2 * pw + 1;
            if (k2h < 0 || k2h > 3 || k2w < 0 || k2w > 3) continue;
            int k2 = k2h * 4 + k2w;
#pragma unroll 8
            for (int m = 0; m < CM; m++)
                acc += g_w2t[k2][m][o] * am_s[g4][qc][m];
        }
        if (acc != 0.f) atomicAdd(&g_ymask[b][p][o], acc);
    }
}

// ---------------------------------------------------------------------------
// Kernel H: final hopfield on y_masked -> output (B, CO, HP, HP)
// grid = BB*NP = 128 blocks, 512 threads; g_KmT coalesced reads (round-8 form)
__global__ void __launch_bounds__(512, 1)
kH(const float* __restrict__ Vm, float* __restrict__ out) {
    int blk = blockIdx.x;
    int b = blk / NP, p = blk % NP;
    __shared__ float yv[CO];
    __shared__ float wexp[NE];
    __shared__ float red16[16];
    __shared__ float red2[8][CO];
    int t = threadIdx.x;
    if (t < CO) yv[t] = g_ymask[b][p][t];
    __syncthreads();
    float l0;
    {
        float acc = 0.f;
#pragma unroll 8
        for (int o = 0; o < CO; o++) acc += g_KmT[o][t] * yv[o];
        l0 = 0.125f * acc;
    }
    float lmax = blockMax512(l0, red16, t);
    float e0 = expf(l0 - lmax);
    wexp[t] = e0;
    float tot = blockSum512(e0, red16, t);
    float inv = 1.f / tot;
    __syncthreads();
    {
        int o = t & 63, g8 = t >> 6;
        float acc = 0.f;
        int k0 = g8 * 64;
#pragma unroll 8
        for (int kk = 0; kk < 64; kk++)
            acc += wexp[k0 + kk] * Vm[(k0 + kk) * CO + o];
        red2[g8][o] = acc;
    }
    __syncthreads();
    if (t < CO) {
        float acc = 0.f;
#pragma unroll
        for (int g = 0; g < 8; g++) acc += red2[g][t];
        out[(b * CO + t) * NP + p] = acc * inv;
    }
}

// ---------------------------------------------------------------------------
extern "C" void kernel_launch(void* const* d_in, const int* in_sizes, int n_in,
                              void* d_out, int out_size) {
    const float* x  = (const float*)d_in[0];  // (2,3,32,32)
    const float* w1 = (const float*)d_in[1];  // (32,3,4,4)
    const float* b1 = (const float*)d_in[2];  // (32,)
    const float* w2 = (const float*)d_in[3];  // (64,32,4,4)
    const float* b2 = (const float*)d_in[4];  // (64,)
    const float* Km = (const float*)d_in[5];  // (512,64)
    const float* Vm = (const float*)d_in[6];  // (512,64)
    float* out = (float*)d_out;               // (2,64,8,8)

    kA<<<128, 256>>>(x, w1, b1, w2, Km);
    kBCDE<<<BB * NP, 512>>>(w1, w2, b2, Km, Vm);
    kFG<<<BB * NI / 4, 256>>>();
    kH<<<BB * NP, 512>>>(Vm, out);
}

// round 16
// speedup vs baseline: 1.1061x; 1.0535x over previous
#include <cuda_runtime.h>
#include <math_constants.h>

// Problem constants
#define BB 2
#define CIN 3
#define HH 32
#define WW 32
#define CM 32      // mid channels
#define HQ 16      // mid spatial
#define CO 64      // out channels
#define HP 8       // out spatial
#define NP 64      // HP*HP
#define NI 1024    // HH*WW
#define NE 512     // num embeddings

// Scratch in device globals (no allocations allowed)
__device__ float g_xw1[BB][HQ][HQ][16][CM];  // per-tap conv1 partials, [k1][m]
__device__ float g_y1[BB][HQ][HQ][CM];       // relu(conv1)
__device__ float g_y[BB][NP][CO];            // relu(conv2)
__device__ float g_v[BB][NP][16][16];        // [k2][k1]
__device__ float g_ymask[BB][NP][CO];
__device__ float g_w2t[16][CM][CO];          // w2 transposed: [k2][m][o] (for kFG)
__device__ float g_KmT[CO][NE];              // K transposed: [o][k] (for kH)

// ---------------------------------------------------------------------------
// Shuffle-based block reductions over 512 threads
__device__ __forceinline__ float blockMax512(float v, float* red16, int t) {
#pragma unroll
    for (int off = 16; off > 0; off >>= 1)
        v = fmaxf(v, __shfl_xor_sync(0xffffffffu, v, off));
    if ((t & 31) == 0) red16[t >> 5] = v;
    __syncthreads();
    if (t < 32) {
        float w = (t < 16) ? red16[t] : -CUDART_INF_F;
#pragma unroll
        for (int off = 8; off > 0; off >>= 1)
            w = fmaxf(w, __shfl_xor_sync(0xffffffffu, w, off));
        if (t == 0) red16[0] = w;
    }
    __syncthreads();
    return red16[0];
}
__device__ __forceinline__ float blockSum512(float v, float* red16, int t) {
#pragma unroll
    for (int off = 16; off > 0; off >>= 1)
        v += __shfl_xor_sync(0xffffffffu, v, off);
    if ((t & 31) == 0) red16[t >> 5] = v;
    __syncthreads();
    if (t < 32) {
        float w = (t < 16) ? red16[t] : 0.f;
#pragma unroll
        for (int off = 8; off > 0; off >>= 1)
            w += __shfl_xor_sync(0xffffffffu, w, off);
        if (t == 0) red16[0] = w;
    }
    __syncthreads();
    return red16[0];
}

// ---------------------------------------------------------------------------
// Kernel A: conv1 per-tap partials + relu(conv1); transposes; zero ymask
// grid = 128 blocks, 256 threads (one thread per (site, m) for conv part)
__global__ void __launch_bounds__(256, 1)
kA(const float* __restrict__ x, const float* __restrict__ w1,
   const float* __restrict__ b1, const float* __restrict__ w2,
   const float* __restrict__ Km) {
    int gid = blockIdx.x * 256 + threadIdx.x;  // 0..32767
    {
        int k2 = gid >> 11, m = (gid >> 6) & 31, o = gid & 63;
        g_w2t[k2][m][o] = w2[(o * CM + m) * 16 + k2];
        int o2 = gid >> 9, kk = gid & 511;
        g_KmT[o2][kk] = Km[kk * CO + o2];
    }
    if (gid < BB * NP * CO) (&g_ymask[0][0][0])[gid] = 0.f;
    if (gid < BB * HQ * HQ * CM) {
        int m = gid & 31;
        int site = gid >> 5;
        int b = site >> 8;
        int q = site & 255;
        int qh = q >> 4, qw = q & 15;
        float acc = b1[m];
#pragma unroll
        for (int k = 0; k < 16; k++) {
            int kh = k >> 2, kw = k & 3;
            int xh = 2 * qh - 1 + kh, xw = 2 * qw - 1 + kw;
            float vv = 0.f;
            if (xh >= 0 && xh < HH && xw >= 0 && xw < WW) {
#pragma unroll
                for (int c = 0; c < CIN; c++)
                    vv += w1[(m * CIN + c) * 16 + k] *
                          x[((b * CIN + c) * HH + xh) * WW + xw];
            }
            g_xw1[b][qh][qw][k][m] = vv;
            acc += vv;
        }
        g_y1[b][qh][qw][m] = fmaxf(acc, 0.f);
    }
}

// ---------------------------------------------------------------------------
// Kernel BCDE: conv2 + relu + hopfield -> rm (smem), then s -> v, per (b,p)
// grid = BB*NP = 128 blocks, 512 threads
struct SmBC {
    float yv[CO];
    float wexp[NE];
    float red2[8][CO];
    float red16[16];
};
struct SmDE {
    float sw[16][512];     // w2 o-tile (16 rows), 32KB
    float w1st[16][33];    // [k1][m], padded
    float smT[16][33];     // [k2][m], padded
};
union SmBCDE { SmBC bc; SmDE de; };

__global__ void __launch_bounds__(512, 1)
kBCDE(const float* __restrict__ w1, const float* __restrict__ w2,
      const float* __restrict__ b2, const float* __restrict__ Km,
      const float* __restrict__ Vm) {
    __shared__ SmBCDE smu;
    __shared__ float y1ps[16][CM];   // [site][m], OOB sites zeroed
    __shared__ float rm_s[CO];
    int t = threadIdx.x;
    int blk = blockIdx.x;
    int b = blk / NP, p = blk % NP;
    int ph = p / HP, pw = p % HP;

    // ---- load y1 patch: one thread per (site, m); coalesced over m ----
    {
        int sk = t >> 5, m = t & 31;
        int qh = 2 * ph - 1 + (sk >> 2);
        int qw = 2 * pw - 1 + (sk & 3);
        float vv = 0.f;
        if (qh >= 0 && qh < HQ && qw >= 0 && qw < HQ) vv = g_y1[b][qh][qw][m];
        y1ps[sk][m] = vv;
    }
    __syncthreads();

    // ---- conv2: o = t&63, g8 = t>>6 handles elements g8*64..+63 of w2 row ----
    {
        int o = t & 63, g8 = t >> 6;
        const float4* w2v = reinterpret_cast<const float4*>(w2 + o * 512 + g8 * 64);
        float acc = 0.f;
#pragma unroll
        for (int j4 = 0; j4 < 16; j4++) {
            float4 wv = w2v[j4];
            int e = g8 * 64 + j4 * 4;
            acc += wv.x * y1ps[(e + 0) & 15][(e + 0) >> 4];
            acc += wv.y * y1ps[(e + 1) & 15][(e + 1) >> 4];
            acc += wv.z * y1ps[(e + 2) & 15][(e + 2) >> 4];
            acc += wv.w * y1ps[(e + 3) & 15][(e + 3) >> 4];
        }
        smu.bc.red2[g8][o] = acc;
    }
    __syncthreads();
    if (t < CO) {
        float acc = b2[t];
#pragma unroll
        for (int g = 0; g < 8; g++) acc += smu.bc.red2[g][t];
        float yy = fmaxf(acc, 0.f);
        smu.bc.yv[t] = yy;
        g_y[b][p][t] = yy;
    }
    __syncthreads();

    // ---- hopfield softmax: 1 key per thread, raw Km row via float4 ----
    float l0;
    {
        const float4* kv = reinterpret_cast<const float4*>(Km + t * CO);
        float acc = 0.f;
#pragma unroll
        for (int j = 0; j < 16; j++) {
            float4 w4 = kv[j];
            acc += w4.x * smu.bc.yv[4 * j] + w4.y * smu.bc.yv[4 * j + 1] +
                   w4.z * smu.bc.yv[4 * j + 2] + w4.w * smu.bc.yv[4 * j + 3];
        }
        l0 = 0.125f * acc;
    }
    float lmax = blockMax512(l0, smu.bc.red16, t);
    float e0 = expf(l0 - lmax);
    smu.bc.wexp[t] = e0;
    float tot = blockSum512(e0, smu.bc.red16, t);
    float inv = 1.f / tot;
    __syncthreads();
    {
        int o = t & 63, g8 = t >> 6;
        float acc = 0.f;
        int k0 = g8 * 64;
#pragma unroll 8
        for (int kk = 0; kk < 64; kk++)
            acc += smu.bc.wexp[k0 + kk] * Vm[(k0 + kk) * CO + o];
        smu.bc.red2[g8][o] = acc;
    }
    __syncthreads();
    if (t < CO) {
        float e = 0.f;
#pragma unroll
        for (int g = 0; g < 8; g++) e += smu.bc.red2[g][t];
        e *= inv;
        float yy = smu.bc.yv[t];
        rm_s[t] = (yy > 0.f) ? 2.f * (yy - e) : 0.f;
    }
    __syncthreads();   // last BC smem read done; union may flip to DE

    // ---- DE: w1st, then s via w2 smem tiles, mask via y1ps, then v ----
    {
        int m = t >> 4, k = t & 15;
        float acc = 0.f;
#pragma unroll
        for (int c = 0; c < CIN; c++) acc += w1[(m * CIN + c) * 16 + k];
        smu.de.w1st[k][m] = acc;
    }
    __syncthreads();
    float sacc = 0.f;
    for (int c = 0; c < 4; c++) {
        {
            const float4* src = reinterpret_cast<const float4*>(w2 + c * 16 * 512);
            float4* dst = reinterpret_cast<float4*>(&smu.de.sw[0][0]);
#pragma unroll
            for (int r = 0; r < 4; r++) dst[r * 512 + t] = src[r * 512 + t];
        }
        __syncthreads();
#pragma unroll
        for (int j = 0; j < 16; j++) sacc += rm_s[c * 16 + j] * smu.de.sw[j][t];
        __syncthreads();
    }
    {
        int m = t >> 4, k2 = t & 15;
        smu.de.smT[k2][m] = (y1ps[k2][m] > 0.f) ? sacc : 0.f;
    }
    __syncthreads();
    if (t < 256) {
        int k2 = t >> 4, k1 = t & 15;
        float a2 = 0.f;
#pragma unroll 8
        for (int m = 0; m < CM; m++)
            a2 += smu.de.smT[k2][m] * smu.de.w1st[k1][m];
        g_v[b][p][k2][k1] = a2;
    }
}

// ---------------------------------------------------------------------------
// Kernel FG: argmin + scatter, 4 pixels per block (all same row ih)
// grid = BB*NI/4 = 512 blocks, 256 threads
__global__ void __launch_bounds__(256, 1)
kFG() {
    __shared__ float am_s[4][4][32];
    __shared__ int selp[4];
    __shared__ float we_s[8];
    __shared__ int wp_s[8];
    int t = threadIdx.x;
    int g4 = t >> 6;
    int pix0 = blockIdx.x * 4;
    int i0 = pix0 & 1023;
    int ih = i0 >> 5;
    int qh0 = (ih + 1) >> 1;

    // ---- argmin: thread t = g4*64 + p ----
    {
        int p = t & 63;
        int pixa = pix0 + g4;
        int ba = pixa >> 10;
        int ia = pixa & 1023;
        int iwa = ia & 31;
        int qw0a = (iwa + 1) >> 1;
        int pha = p >> 3, pwa = p & 7;
        float e = 0.f;
#pragma unroll
        for (int qc = 0; qc < 2; qc++) {
            int qh = qh0 - qc;
            int k2h = qh - 2 * pha + 1;
            if (qh < 0 || qh >= HQ || k2h < 0 || k2h > 3) continue;
            int k1h = ih + 1 - 2 * qh;
#pragma unroll
            for (int dqw = 0; dqw < 2; dqw++) {
                int qw = qw0a - dqw;
                int k2w = qw - 2 * pwa + 1;
                if (qw < 0 || qw >= HQ || k2w < 0 || k2w > 3) continue;
                e += g_v[ba][p][k2h * 4 + k2w][k1h * 4 + (iwa + 1 - 2 * qw)];
            }
        }
        float be = e;
        int bp = p;
#pragma unroll
        for (int off = 16; off > 0; off >>= 1) {
            float eo = __shfl_xor_sync(0xffffffffu, be, off);
            int po = __shfl_xor_sync(0xffffffffu, bp, off);
            if (eo < be || (eo == be && po < bp)) { be = eo; bp = po; }
        }
        if ((t & 31) == 0) { we_s[t >> 5] = be; wp_s[t >> 5] = bp; }
    }
    __syncthreads();
    if (t < 4) {
        float e0 = we_s[t * 2], e1 = we_s[t * 2 + 1];
        int p0 = wp_s[t * 2], p1 = wp_s[t * 2 + 1];
        selp[t] = (e1 < e0 || (e1 == e0 && p1 < p0)) ? p1 : p0;
    }
    __syncthreads();

    // ---- scatter contrib into ymask ----
    int o = t & 63;
    int pix = pix0 + g4;
    int b = pix >> 10;
    int i = pix & 1023;
    int iw = i & 31;
    int qw0 = (iw + 1) >> 1;
    int p = selp[g4];
    int ph = p >> 3, pw = p & 7;
#pragma unroll
    for (int rep = 0; rep < 2; rep++) {
        int e2 = rep * 64 + o;
        int qc = e2 >> 5, m = e2 & 31;
        int qh = qh0 - (qc >> 1), qw = qw0 - (qc & 1);
        float vv = 0.f;
        if (qh >= 0 && qh < HQ && qw >= 0 && qw < HQ) {
            int k2h = qh - 2 * ph + 1, k2w = qw - 2 * pw + 1;
            if (k2h >= 0 && k2h <= 3 && k2w >= 0 && k2w <= 3) {
                if (g_y1[b][qh][qw][m] > 0.f) {
                    int k1 = (ih + 1 - 2 * qh) * 4 + (iw + 1 - 2 * qw);
                    vv = g_xw1[b][qh][qw][k1][m];
                }
            }
        }
        am_s[g4][qc][m] = vv;
    }
    __syncthreads();
    float yy = g_y[b][p][o];
    if (yy > 0.f) {
        float acc = 0.f;
#pragma unroll
        for (int qc = 0; qc < 4; qc++) {
            int qh = qh0 - (qc >> 1), qw = qw0 - (qc & 1);
            if (qh < 0 || qh >= HQ || qw < 0 || qw >= HQ) continue;
            int k2h = qh - 2 * ph + 1, k2w = qw - 2 * pw + 1;
            if (k2h < 0 || k2h > 3 || k2w < 0 || k2w > 3) continue;
            int k2 = k2h * 4 + k2w;
#pragma unroll 8
            for (int m = 0; m < CM; m++)
                acc += g_w2t[k2][m][o] * am_s[g4][qc][m];
        }
        if (acc != 0.f) atomicAdd(&g_ymask[b][p][o], acc);
    }
}

// ---------------------------------------------------------------------------
// Kernel H: final hopfield on y_masked -> output (B, CO, HP, HP)
// grid = BB*NP = 128 blocks, 512 threads
__global__ void __launch_bounds__(512, 1)
kH(const float* __restrict__ Vm, float* __restrict__ out) {
    int blk = blockIdx.x;
    int b = blk / NP, p = blk % NP;
    __shared__ float yv[CO];
    __shared__ float wexp[NE];
    __shared__ float red16[16];
    __shared__ float red2[8][CO];
    int t = threadIdx.x;
    if (t < CO) yv[t] = g_ymask[b][p][t];
    __syncthreads();
    float l0;
    {
        float acc = 0.f;
#pragma unroll 8
        for (int o = 0; o < CO; o++) acc += g_KmT[o][t] * yv[o];
        l0 = 0.125f * acc;
    }
    float lmax = blockMax512(l0, red16, t);
    float e0 = expf(l0 - lmax);
    wexp[t] = e0;
    float tot = blockSum512(e0, red16, t);
    float inv = 1.f / tot;
    __syncthreads();
    {
        int o = t & 63, g8 = t >> 6;
        float acc = 0.f;
        int k0 = g8 * 64;
#pragma unroll 8
        for (int kk = 0; kk < 64; kk++)
            acc += wexp[k0 + kk] * Vm[(k0 + kk) * CO + o];
        red2[g8][o] = acc;
    }
    __syncthreads();
    if (t < CO) {
        float acc = 0.f;
#pragma unroll
        for (int g = 0; g < 8; g++) acc += red2[g][t];
        out[(b * CO + t) * NP + p] = acc * inv;
    }
}

// ---------------------------------------------------------------------------
extern "C" void kernel_launch(void* const* d_in, const int* in_sizes, int n_in,
                              void* d_out, int out_size) {
    const float* x  = (const float*)d_in[0];  // (2,3,32,32)
    const float* w1 = (const float*)d_in[1];  // (32,3,4,4)
    const float* b1 = (const float*)d_in[2];  // (32,)
    const float* w2 = (const float*)d_in[3];  // (64,32,4,4)
    const float* b2 = (const float*)d_in[4];  // (64,)
    const float* Km = (const float*)d_in[5];  // (512,64)
    const float* Vm = (const float*)d_in[6];  // (512,64)
    float* out = (float*)d_out;               // (2,64,8,8)

    kA<<<128, 256>>>(x, w1, b1, w2, Km);
    kBCDE<<<BB * NP, 512>>>(w1, w2, b2, Km, Vm);
    kFG<<<BB * NI / 4, 256>>>();
    kH<<<BB * NP, 512>>>(Vm, out);
}